// round 15
// baseline (speedup 1.0000x reference)
#include <cuda_runtime.h>
#include <cuda_fp16.h>
#include <math.h>
#include <stdint.h>

#define D_MODEL 1024
#define D_INNER 2048
#define M_TOK   16384
#define N1      4096
#define K1      1024
#define N2      1024
#define K2      2048
#define LN_EPS  1e-5f

__device__ __half g_xn  [(size_t)M_TOK * K1];
__device__ __half g_win [(size_t)N1 * K1];
__device__ __half g_wout[(size_t)N2 * K2];
__device__ __half g_xz  [(size_t)M_TOK * N1];
__device__ __half g_y   [(size_t)M_TOK * K2];
__device__ float  g_cwt [4 * D_INNER];

#define PDL_WAIT()  asm volatile("griddepcontrol.wait;" ::: "memory")
#define PDL_FIRE()  asm volatile("griddepcontrol.launch_dependents;")

// ---- fp16 GEMM: C[M,N]=A[M,K]*B[N,K]^T, 128x128x32, 128 thr,
//      4 warps x (64x64), 4-stage cp.async, 1 sync/iter + PDL ----
#define BK          32
#define SM_STRIDE   40
#define ARR_BYTES   (128 * SM_STRIDE * 2)   // 10240
#define STAGE_BYTES (2 * ARR_BYTES)         // 20480
#define NSTAGE      4
#define SMEM_DYN    (NSTAGE * STAGE_BYTES)  // 81920

#define LDSM4(R0, R1, R2, R3, ADDR)                                          \
    asm volatile("ldmatrix.sync.aligned.m8n8.x4.shared.b16 {%0,%1,%2,%3},[%4];" \
                 : "=r"(R0), "=r"(R1), "=r"(R2), "=r"(R3) : "r"(ADDR))
#define MMA16816(C, A, B0, B1)                                               \
    asm volatile("mma.sync.aligned.m16n8k16.row.col.f32.f16.f16.f32 "         \
                 "{%0,%1,%2,%3},{%4,%5,%6,%7},{%8,%9},{%0,%1,%2,%3};"         \
                 : "+f"((C)[0]), "+f"((C)[1]), "+f"((C)[2]), "+f"((C)[3])     \
                 : "r"((A)[0]), "r"((A)[1]), "r"((A)[2]), "r"((A)[3]),        \
                   "r"(B0), "r"(B1))
#define CP16(dst, src) \
    asm volatile("cp.async.cg.shared.global [%0], [%1], 16;" :: "r"(dst), "l"(src))

// OUT_HALF=1: GEMM1 (primary=prep; no pre-wait loads).
// OUT_HALF=0: GEMM2 (primary=conv; B=W_out from prep -> pre-wait B prefetch).
template <bool OUT_HALF>
__global__ __launch_bounds__(128, 2) void gemm_f16(
    const __half* __restrict__ A, const __half* __restrict__ B,
    void* __restrict__ Cv, const float* __restrict__ R, int K, int Nn)
{
    extern __shared__ __align__(16) char smem[];
    const uint32_t sbase = (uint32_t)__cvta_generic_to_shared(smem);
    const int tid = threadIdx.x;
    const int bm = blockIdx.y, bn = blockIdx.x;
    const int nk = K >> 5;

    const __half* gA = A + (size_t)bm * 128 * K;
    const __half* gB = B + (size_t)bn * 128 * K;

    float acc[4][8][4];
    #pragma unroll
    for (int a = 0; a < 4; a++)
        #pragma unroll
        for (int b = 0; b < 8; b++)
            #pragma unroll
            for (int c = 0; c < 4; c++) acc[a][b][c] = 0.f;

    const int lr = tid >> 2, lc = (tid & 3) * 8;

    auto load_A = [&](int s, int kt) {
        uint32_t so = sbase + s * STAGE_BYTES;
        #pragma unroll
        for (int i = 0; i < 4; i++) {
            int r = i * 32 + lr;
            CP16(so + (uint32_t)(r * SM_STRIDE + lc) * 2u,
                 gA + (size_t)r * K + kt * BK + lc);
        }
    };
    auto load_B = [&](int s, int kt) {
        uint32_t so = sbase + s * STAGE_BYTES + ARR_BYTES;
        #pragma unroll
        for (int i = 0; i < 4; i++) {
            int r = i * 32 + lr;
            CP16(so + (uint32_t)(r * SM_STRIDE + lc) * 2u,
                 gB + (size_t)r * K + kt * BK + lc);
        }
    };

    if (!OUT_HALF) {   // prefetch W_out tiles while primary (conv) drains
        load_B(0, 0); load_B(1, 1); load_B(2, 2);
    }
    PDL_WAIT();
    if (OUT_HALF) {
        #pragma unroll
        for (int p = 0; p < 3; p++) {
            load_A(p, p); load_B(p, p);
            asm volatile("cp.async.commit_group;");
        }
    } else {
        load_A(0, 0); asm volatile("cp.async.commit_group;");
        load_A(1, 1); asm volatile("cp.async.commit_group;");
        load_A(2, 2); asm volatile("cp.async.commit_group;");
    }

    const int wid = tid >> 5, lane = tid & 31;
    const int wm = (wid >> 1) << 6;
    const int wn = (wid & 1) << 6;
    const int arow = wm + (lane & 15);
    const int brow = wn + ((lane >> 4) & 1) * 8 + (lane & 7);

    auto compute = [&](int s) {
        uint32_t base = sbase + s * STAGE_BYTES;
        #pragma unroll
        for (int ks = 0; ks < 2; ks++) {
            uint32_t ah[4][4], bh[8][2];
            int acol = ks * 16 + (lane >> 4) * 8;
            #pragma unroll
            for (int mi = 0; mi < 4; mi++) {
                uint32_t ad = base + (uint32_t)(((arow + mi * 16) * SM_STRIDE + acol) << 1);
                LDSM4(ah[mi][0], ah[mi][1], ah[mi][2], ah[mi][3], ad);
            }
            int bcol = ks * 16 + ((lane >> 3) & 1) * 8;
            #pragma unroll
            for (int p = 0; p < 4; p++) {
                uint32_t bd = base + ARR_BYTES +
                              (uint32_t)(((brow + p * 16) * SM_STRIDE + bcol) << 1);
                uint32_t r0, r1, r2, r3;
                LDSM4(r0, r1, r2, r3, bd);
                bh[2 * p][0] = r0; bh[2 * p][1] = r1;
                bh[2 * p + 1][0] = r2; bh[2 * p + 1][1] = r3;
            }
            #pragma unroll
            for (int mi = 0; mi < 4; mi++)
                #pragma unroll
                for (int ni = 0; ni < 8; ni++)
                    MMA16816(acc[mi][ni], ah[mi], bh[ni][0], bh[ni][1]);
        }
    };

    for (int kt = 0; kt < nk; kt++) {
        asm volatile("cp.async.wait_group 2;");
        __syncthreads();
        if (kt + 3 < nk) { load_A((kt + 3) & 3, kt + 3); load_B((kt + 3) & 3, kt + 3); }
        asm volatile("cp.async.commit_group;");
        compute(kt & 3);
    }

    const int g = lane >> 2, tq = (lane & 3) * 2;
    #pragma unroll
    for (int mi = 0; mi < 4; mi++)
        #pragma unroll
        for (int ni = 0; ni < 8; ni++) {
            int row = bm * 128 + wm + mi * 16 + g;
            int col = bn * 128 + wn + ni * 8 + tq;
            if (OUT_HALF) {
                __half* C = (__half*)Cv;
                *reinterpret_cast<__half2*>(C + (size_t)row * Nn + col) =
                    __floats2half2_rn(acc[mi][ni][0], acc[mi][ni][1]);
                *reinterpret_cast<__half2*>(C + (size_t)(row + 8) * Nn + col) =
                    __floats2half2_rn(acc[mi][ni][2], acc[mi][ni][3]);
            } else {
                float* C = (float*)Cv;
                float2 r0 = *reinterpret_cast<const float2*>(R + (size_t)row * Nn + col);
                float2 r1 = *reinterpret_cast<const float2*>(R + (size_t)(row + 8) * Nn + col);
                *reinterpret_cast<float2*>(C + (size_t)row * Nn + col) =
                    make_float2(acc[mi][ni][0] + r0.x, acc[mi][ni][1] + r0.y);
                *reinterpret_cast<float2*>(C + (size_t)(row + 8) * Nn + col) =
                    make_float2(acc[mi][ni][2] + r1.x, acc[mi][ni][3] + r1.y);
            }
        }
    PDL_FIRE();
}

// ---------------- fused prep ----------------
#define LN_BLKS   M_TOK
#define F2H_IN    (N1 * K1 / 1024)
#define F2H_OUT   (N2 * K2 / 1024)
#define TR_BLKS   32
#define PREP_GRID (LN_BLKS + F2H_IN + F2H_OUT + TR_BLKS)

__device__ __forceinline__ void f2h_block(const float* __restrict__ src,
                                          __half* __restrict__ dst, int blk) {
    int i = blk * 256 + threadIdx.x;
    float4 v = reinterpret_cast<const float4*>(src)[i];
    reinterpret_cast<__half2*>(dst)[2 * i]     = __floats2half2_rn(v.x, v.y);
    reinterpret_cast<__half2*>(dst)[2 * i + 1] = __floats2half2_rn(v.z, v.w);
}

__global__ __launch_bounds__(256) void prep(
    const float* __restrict__ x, const float* __restrict__ gamma,
    const float* __restrict__ beta, __half* __restrict__ xh,
    const float* __restrict__ W_in,  __half* __restrict__ win_h,
    const float* __restrict__ W_out, __half* __restrict__ wout_h,
    const float* __restrict__ cw, float* __restrict__ cwt)
{
    int b = blockIdx.x;
    if (b < LN_BLKS) {
        int row = b, tid = threadIdx.x;
        const float4 v = reinterpret_cast<const float4*>(x + (size_t)row * D_MODEL)[tid];
        float s  = v.x + v.y + v.z + v.w;
        float ss = v.x*v.x + v.y*v.y + v.z*v.z + v.w*v.w;
        #pragma unroll
        for (int o = 16; o; o >>= 1) {
            s  += __shfl_xor_sync(0xffffffffu, s,  o);
            ss += __shfl_xor_sync(0xffffffffu, ss, o);
        }
        __shared__ float rs[8], rq[8], mv[2];
        int w = tid >> 5, lane = tid & 31;
        if (lane == 0) { rs[w] = s; rq[w] = ss; }
        __syncthreads();
        if (tid == 0) {
            float a = 0.f, bb = 0.f;
            #pragma unroll
            for (int i = 0; i < 8; i++) { a += rs[i]; bb += rq[i]; }
            float mu = a * (1.f / D_MODEL);
            float var = bb * (1.f / D_MODEL) - mu * mu;
            mv[0] = mu; mv[1] = rsqrtf(var + LN_EPS);
        }
        __syncthreads();
        float mu = mv[0], rstd = mv[1];
        const float4 gv = reinterpret_cast<const float4*>(gamma)[tid];
        const float4 bv = reinterpret_cast<const float4*>(beta)[tid];
        __half2* out = (__half2*)(xh + (size_t)row * D_MODEL) + tid * 2;
        out[0] = __floats2half2_rn((v.x - mu) * rstd * gv.x + bv.x,
                                   (v.y - mu) * rstd * gv.y + bv.y);
        out[1] = __floats2half2_rn((v.z - mu) * rstd * gv.z + bv.z,
                                   (v.w - mu) * rstd * gv.w + bv.w);
    } else if (b < LN_BLKS + F2H_IN) {
        f2h_block(W_in, win_h, b - LN_BLKS);
    } else if (b < LN_BLKS + F2H_IN + F2H_OUT) {
        f2h_block(W_out, wout_h, b - LN_BLKS - F2H_IN);
    } else {
        int i = (b - LN_BLKS - F2H_IN - F2H_OUT) * 256 + threadIdx.x;
        if (i < 4 * D_INNER) {
            int c = i >> 2, j = i & 3;
            cwt[j * D_INNER + c] = cw[i];
        }
    }
    PDL_FIRE();
}

__device__ __forceinline__ float silu(float v) {
    return v / (1.f + __expf(-v));
}

__global__ __launch_bounds__(256) void conv_gate(
    const __half* __restrict__ xz, const float* __restrict__ cwt,
    const float* __restrict__ cb, __half* __restrict__ y)
{
    int tid = threadIdx.x;
    int m   = blockIdx.x;
    int t   = m & 4095;
    int c   = tid * 8;
    size_t base = (size_t)m * N1 + c;

    // pre-wait loads: cwt/cb come from prep (grand-primary), not GEMM1
    float a[8];
    const float4* cbv = reinterpret_cast<const float4*>(cb + c);
    float4 cb0 = cbv[0], cb1 = cbv[1];
    float4 w0[4], w1[4];
    #pragma unroll
    for (int j = 0; j < 4; j++) {
        w0[j] = *reinterpret_cast<const float4*>(cwt + j * D_INNER + c);
        w1[j] = *reinterpret_cast<const float4*>(cwt + j * D_INNER + c + 4);
    }
    PDL_WAIT();

    a[0]=cb0.x; a[1]=cb0.y; a[2]=cb0.z; a[3]=cb0.w;
    a[4]=cb1.x; a[5]=cb1.y; a[6]=cb1.z; a[7]=cb1.w;

    #pragma unroll
    for (int j = 0; j < 4; j++) {
        if (t - 3 + j >= 0) {
            float4 raw = *reinterpret_cast<const float4*>(
                xz + base - (size_t)(3 - j) * N1);
            float2 f0 = __half22float2(*(__half2*)&raw.x);
            float2 f1 = __half22float2(*(__half2*)&raw.y);
            float2 f2 = __half22float2(*(__half2*)&raw.z);
            float2 f3 = __half22float2(*(__half2*)&raw.w);
            a[0] += w0[j].x*f0.x; a[1] += w0[j].y*f0.y;
            a[2] += w0[j].z*f1.x; a[3] += w0[j].w*f1.y;
            a[4] += w1[j].x*f2.x; a[5] += w1[j].y*f2.y;
            a[6] += w1[j].z*f3.x; a[7] += w1[j].w*f3.y;
        }
    }

    float4 zraw = *reinterpret_cast<const float4*>(xz + base + D_INNER);
    float zf[8];
    { float2 q = __half22float2(*(__half2*)&zraw.x); zf[0]=q.x; zf[1]=q.y; }
    { float2 q = __half22float2(*(__half2*)&zraw.y); zf[2]=q.x; zf[3]=q.y; }
    { float2 q = __half22float2(*(__half2*)&zraw.z); zf[4]=q.x; zf[5]=q.y; }
    { float2 q = __half22float2(*(__half2*)&zraw.w); zf[6]=q.x; zf[7]=q.y; }

    __half2 o[4];
    #pragma unroll
    for (int i = 0; i < 4; i++)
        o[i] = __floats2half2_rn(silu(a[2*i]) * silu(zf[2*i]),
                                 silu(a[2*i+1]) * silu(zf[2*i+1]));
    *reinterpret_cast<float4*>(y + (size_t)m * D_INNER + c) = *(float4*)o;
    PDL_FIRE();
}

extern "C" void kernel_launch(void* const* d_in, const int* in_sizes, int n_in,
                              void* d_out, int out_size)
{
    const float* x     = (const float*)d_in[0];
    const float* gamma = (const float*)d_in[1];
    const float* beta  = (const float*)d_in[2];
    const float* W_in  = (const float*)d_in[3];
    const float* cw    = (const float*)d_in[4];
    const float* cb    = (const float*)d_in[5];
    const float* W_out = (const float*)d_in[6];
    float* out = (float*)d_out;

    void *p_xn, *p_win, *p_wout, *p_xz, *p_y, *p_cwt;
    cudaGetSymbolAddress(&p_xn,   g_xn);
    cudaGetSymbolAddress(&p_win,  g_win);
    cudaGetSymbolAddress(&p_wout, g_wout);
    cudaGetSymbolAddress(&p_xz,   g_xz);
    cudaGetSymbolAddress(&p_y,    g_y);
    cudaGetSymbolAddress(&p_cwt,  g_cwt);

    cudaFuncSetAttribute(gemm_f16<true>,
        cudaFuncAttributeMaxDynamicSharedMemorySize, SMEM_DYN);
    cudaFuncSetAttribute(gemm_f16<false>,
        cudaFuncAttributeMaxDynamicSharedMemorySize, SMEM_DYN);

    prep<<<PREP_GRID, 256>>>(x, gamma, beta, (__half*)p_xn,
        W_in, (__half*)p_win, W_out, (__half*)p_wout, cw, (float*)p_cwt);

    cudaLaunchAttribute pdl[1];
    pdl[0].id = cudaLaunchAttributeProgrammaticStreamSerialization;
    pdl[0].val.programmaticStreamSerializationAllowed = 1;

    {   // GEMM1
        cudaLaunchConfig_t cfg = {};
        cfg.gridDim = dim3(N1 / 128, M_TOK / 128);
        cfg.blockDim = dim3(128);
        cfg.dynamicSmemBytes = SMEM_DYN;
        cfg.stream = 0;
        cfg.attrs = pdl; cfg.numAttrs = 1;
        cudaLaunchKernelEx(&cfg, gemm_f16<true>,
            (const __half*)p_xn, (const __half*)p_win,
            (void*)p_xz, (const float*)nullptr, (int)K1, (int)N1);
    }
    {   // conv_gate
        cudaLaunchConfig_t cfg = {};
        cfg.gridDim = dim3(M_TOK);
        cfg.blockDim = dim3(256);
        cfg.stream = 0;
        cfg.attrs = pdl; cfg.numAttrs = 1;
        cudaLaunchKernelEx(&cfg, conv_gate,
            (const __half*)p_xz, (const float*)p_cwt, cb, (__half*)p_y);
    }
    {   // GEMM2
        cudaLaunchConfig_t cfg = {};
        cfg.gridDim = dim3(N2 / 128, M_TOK / 128);
        cfg.blockDim = dim3(128);
        cfg.dynamicSmemBytes = SMEM_DYN;
        cfg.stream = 0;
        cfg.attrs = pdl; cfg.numAttrs = 1;
        cudaLaunchKernelEx(&cfg, gemm_f16<false>,
            (const __half*)p_y, (const __half*)p_wout,
            (void*)out, (const float*)x, (int)K2, (int)N2);
    }
}

// round 16
// speedup vs baseline: 1.1877x; 1.1877x over previous
#include <cuda_runtime.h>
#include <cuda_fp16.h>
#include <math.h>
#include <stdint.h>

#define D_MODEL 1024
#define D_INNER 2048
#define M_TOK   16384
#define N1      4096
#define K1      1024
#define N2      1024
#define K2      2048
#define LN_EPS  1e-5f

__device__ __half g_xn  [(size_t)M_TOK * K1];
__device__ __half g_win [(size_t)N1 * K1];
__device__ __half g_wout[(size_t)N2 * K2];
__device__ __half g_xz  [(size_t)M_TOK * N1];
__device__ __half g_y   [(size_t)M_TOK * K2];
__device__ float  g_cwt [4 * D_INNER];

#define PDL_WAIT()  asm volatile("griddepcontrol.wait;" ::: "memory")
#define PDL_FIRE()  asm volatile("griddepcontrol.launch_dependents;")

// ---- fp16 GEMM (R14 config, unchanged): 128x128x32, 128 thr,
//      4 warps x (64x64), 4-stage cp.async, 1 sync/iter ----
#define BK          32
#define SM_STRIDE   40
#define ARR_BYTES   (128 * SM_STRIDE * 2)   // 10240
#define STAGE_BYTES (2 * ARR_BYTES)         // 20480
#define NSTAGE      4
#define SMEM_DYN    (NSTAGE * STAGE_BYTES)  // 81920

#define LDSM4(R0, R1, R2, R3, ADDR)                                          \
    asm volatile("ldmatrix.sync.aligned.m8n8.x4.shared.b16 {%0,%1,%2,%3},[%4];" \
                 : "=r"(R0), "=r"(R1), "=r"(R2), "=r"(R3) : "r"(ADDR))
#define MMA16816(C, A, B0, B1)                                               \
    asm volatile("mma.sync.aligned.m16n8k16.row.col.f32.f16.f16.f32 "         \
                 "{%0,%1,%2,%3},{%4,%5,%6,%7},{%8,%9},{%0,%1,%2,%3};"         \
                 : "+f"((C)[0]), "+f"((C)[1]), "+f"((C)[2]), "+f"((C)[3])     \
                 : "r"((A)[0]), "r"((A)[1]), "r"((A)[2]), "r"((A)[3]),        \
                   "r"(B0), "r"(B1))
#define CP16(dst, src) \
    asm volatile("cp.async.cg.shared.global [%0], [%1], 16;" :: "r"(dst), "l"(src))

template <bool OUT_HALF>
__global__ __launch_bounds__(128, 2) void gemm_f16(
    const __half* __restrict__ A, const __half* __restrict__ B,
    void* __restrict__ Cv, const float* __restrict__ R, int K, int Nn)
{
    PDL_WAIT();
    extern __shared__ __align__(16) char smem[];
    const uint32_t sbase = (uint32_t)__cvta_generic_to_shared(smem);
    const int tid = threadIdx.x;
    const int bm = blockIdx.y, bn = blockIdx.x;
    const int nk = K >> 5;

    const __half* gA = A + (size_t)bm * 128 * K;
    const __half* gB = B + (size_t)bn * 128 * K;

    float acc[4][8][4];
    #pragma unroll
    for (int a = 0; a < 4; a++)
        #pragma unroll
        for (int b = 0; b < 8; b++)
            #pragma unroll
            for (int c = 0; c < 4; c++) acc[a][b][c] = 0.f;

    const int lr = tid >> 2, lc = (tid & 3) * 8;

    auto load_stage = [&](int s, int kt) {
        uint32_t so = sbase + s * STAGE_BYTES;
        #pragma unroll
        for (int i = 0; i < 4; i++) {
            int r = i * 32 + lr;
            uint32_t dst = so + (uint32_t)(r * SM_STRIDE + lc) * 2u;
            CP16(dst,             gA + (size_t)r * K + kt * BK + lc);
            CP16(dst + ARR_BYTES, gB + (size_t)r * K + kt * BK + lc);
        }
    };

    const int wid = tid >> 5, lane = tid & 31;
    const int wm = (wid >> 1) << 6;
    const int wn = (wid & 1) << 6;
    const int arow = wm + (lane & 15);
    const int brow = wn + ((lane >> 4) & 1) * 8 + (lane & 7);

    auto compute = [&](int s) {
        uint32_t base = sbase + s * STAGE_BYTES;
        #pragma unroll
        for (int ks = 0; ks < 2; ks++) {
            uint32_t ah[4][4], bh[8][2];
            int acol = ks * 16 + (lane >> 4) * 8;
            #pragma unroll
            for (int mi = 0; mi < 4; mi++) {
                uint32_t ad = base + (uint32_t)(((arow + mi * 16) * SM_STRIDE + acol) << 1);
                LDSM4(ah[mi][0], ah[mi][1], ah[mi][2], ah[mi][3], ad);
            }
            int bcol = ks * 16 + ((lane >> 3) & 1) * 8;
            #pragma unroll
            for (int p = 0; p < 4; p++) {
                uint32_t bd = base + ARR_BYTES +
                              (uint32_t)(((brow + p * 16) * SM_STRIDE + bcol) << 1);
                uint32_t r0, r1, r2, r3;
                LDSM4(r0, r1, r2, r3, bd);
                bh[2 * p][0] = r0; bh[2 * p][1] = r1;
                bh[2 * p + 1][0] = r2; bh[2 * p + 1][1] = r3;
            }
            #pragma unroll
            for (int mi = 0; mi < 4; mi++)
                #pragma unroll
                for (int ni = 0; ni < 8; ni++)
                    MMA16816(acc[mi][ni], ah[mi], bh[ni][0], bh[ni][1]);
        }
    };

    #pragma unroll
    for (int p = 0; p < 3; p++) {
        load_stage(p, p);
        asm volatile("cp.async.commit_group;");
    }
    for (int kt = 0; kt < nk; kt++) {
        asm volatile("cp.async.wait_group 2;");
        __syncthreads();
        if (kt + 3 < nk) load_stage((kt + 3) & 3, kt + 3);
        asm volatile("cp.async.commit_group;");
        compute(kt & 3);
    }

    const int g = lane >> 2, tq = (lane & 3) * 2;
    #pragma unroll
    for (int mi = 0; mi < 4; mi++)
        #pragma unroll
        for (int ni = 0; ni < 8; ni++) {
            int row = bm * 128 + wm + mi * 16 + g;
            int col = bn * 128 + wn + ni * 8 + tq;
            if (OUT_HALF) {
                __half* C = (__half*)Cv;
                *reinterpret_cast<__half2*>(C + (size_t)row * Nn + col) =
                    __floats2half2_rn(acc[mi][ni][0], acc[mi][ni][1]);
                *reinterpret_cast<__half2*>(C + (size_t)(row + 8) * Nn + col) =
                    __floats2half2_rn(acc[mi][ni][2], acc[mi][ni][3]);
            } else {
                float* C = (float*)Cv;
                float2 r0 = *reinterpret_cast<const float2*>(R + (size_t)row * Nn + col);
                float2 r1 = *reinterpret_cast<const float2*>(R + (size_t)(row + 8) * Nn + col);
                *reinterpret_cast<float2*>(C + (size_t)row * Nn + col) =
                    make_float2(acc[mi][ni][0] + r0.x, acc[mi][ni][1] + r0.y);
                *reinterpret_cast<float2*>(C + (size_t)(row + 8) * Nn + col) =
                    make_float2(acc[mi][ni][2] + r1.x, acc[mi][ni][3] + r1.y);
            }
        }
    PDL_FIRE();
}

// ---------------- fused prep ----------------
#define LN_BLKS   M_TOK
#define F2H_IN    (N1 * K1 / 1024)
#define F2H_OUT   (N2 * K2 / 1024)
#define TR_BLKS   32
#define PREP_GRID (LN_BLKS + F2H_IN + F2H_OUT + TR_BLKS)

__device__ __forceinline__ void f2h_block(const float* __restrict__ src,
                                          __half* __restrict__ dst, int blk) {
    int i = blk * 256 + threadIdx.x;
    float4 v = reinterpret_cast<const float4*>(src)[i];
    reinterpret_cast<__half2*>(dst)[2 * i]     = __floats2half2_rn(v.x, v.y);
    reinterpret_cast<__half2*>(dst)[2 * i + 1] = __floats2half2_rn(v.z, v.w);
}

__global__ __launch_bounds__(256) void prep(
    const float* __restrict__ x, const float* __restrict__ gamma,
    const float* __restrict__ beta, __half* __restrict__ xh,
    const float* __restrict__ W_in,  __half* __restrict__ win_h,
    const float* __restrict__ W_out, __half* __restrict__ wout_h,
    const float* __restrict__ cw, float* __restrict__ cwt)
{
    int b = blockIdx.x;
    if (b < LN_BLKS) {
        int row = b, tid = threadIdx.x;
        const float4 v = reinterpret_cast<const float4*>(x + (size_t)row * D_MODEL)[tid];
        float s  = v.x + v.y + v.z + v.w;
        float ss = v.x*v.x + v.y*v.y + v.z*v.z + v.w*v.w;
        #pragma unroll
        for (int o = 16; o; o >>= 1) {
            s  += __shfl_xor_sync(0xffffffffu, s,  o);
            ss += __shfl_xor_sync(0xffffffffu, ss, o);
        }
        __shared__ float rs[8], rq[8], mv[2];
        int w = tid >> 5, lane = tid & 31;
        if (lane == 0) { rs[w] = s; rq[w] = ss; }
        __syncthreads();
        if (tid == 0) {
            float a = 0.f, bb = 0.f;
            #pragma unroll
            for (int i = 0; i < 8; i++) { a += rs[i]; bb += rq[i]; }
            float mu = a * (1.f / D_MODEL);
            float var = bb * (1.f / D_MODEL) - mu * mu;
            mv[0] = mu; mv[1] = rsqrtf(var + LN_EPS);
        }
        __syncthreads();
        float mu = mv[0], rstd = mv[1];
        const float4 gv = reinterpret_cast<const float4*>(gamma)[tid];
        const float4 bv = reinterpret_cast<const float4*>(beta)[tid];
        __half2* out = (__half2*)(xh + (size_t)row * D_MODEL) + tid * 2;
        out[0] = __floats2half2_rn((v.x - mu) * rstd * gv.x + bv.x,
                                   (v.y - mu) * rstd * gv.y + bv.y);
        out[1] = __floats2half2_rn((v.z - mu) * rstd * gv.z + bv.z,
                                   (v.w - mu) * rstd * gv.w + bv.w);
    } else if (b < LN_BLKS + F2H_IN) {
        f2h_block(W_in, win_h, b - LN_BLKS);
    } else if (b < LN_BLKS + F2H_IN + F2H_OUT) {
        f2h_block(W_out, wout_h, b - LN_BLKS - F2H_IN);
    } else {
        int i = (b - LN_BLKS - F2H_IN - F2H_OUT) * 256 + threadIdx.x;
        if (i < 4 * D_INNER) {
            int c = i >> 2, j = i & 3;
            cwt[j * D_INNER + c] = cw[i];
        }
    }
    PDL_FIRE();
}

__device__ __forceinline__ float silu(float v) {
    return v / (1.f + __expf(-v));
}

__global__ __launch_bounds__(256) void conv_gate(
    const __half* __restrict__ xz, const float* __restrict__ cwt,
    const float* __restrict__ cb, __half* __restrict__ y)
{
    PDL_WAIT();
    int tid = threadIdx.x;
    int m   = blockIdx.x;
    int t   = m & 4095;
    int c   = tid * 8;
    size_t base = (size_t)m * N1 + c;

    float a[8];
    const float4* cbv = reinterpret_cast<const float4*>(cb + c);
    float4 cb0 = cbv[0], cb1 = cbv[1];
    a[0]=cb0.x; a[1]=cb0.y; a[2]=cb0.z; a[3]=cb0.w;
    a[4]=cb1.x; a[5]=cb1.y; a[6]=cb1.z; a[7]=cb1.w;

    #pragma unroll
    for (int j = 0; j < 4; j++) {
        if (t - 3 + j >= 0) {
            float4 w0 = *reinterpret_cast<const float4*>(cwt + j * D_INNER + c);
            float4 w1 = *reinterpret_cast<const float4*>(cwt + j * D_INNER + c + 4);
            float4 raw = *reinterpret_cast<const float4*>(
                xz + base - (size_t)(3 - j) * N1);
            float2 f0 = __half22float2(*(__half2*)&raw.x);
            float2 f1 = __half22float2(*(__half2*)&raw.y);
            float2 f2 = __half22float2(*(__half2*)&raw.z);
            float2 f3 = __half22float2(*(__half2*)&raw.w);
            a[0] += w0.x*f0.x; a[1] += w0.y*f0.y;
            a[2] += w0.z*f1.x; a[3] += w0.w*f1.y;
            a[4] += w1.x*f2.x; a[5] += w1.y*f2.y;
            a[6] += w1.z*f3.x; a[7] += w1.w*f3.y;
        }
    }

    float4 zraw = *reinterpret_cast<const float4*>(xz + base + D_INNER);
    float zf[8];
    { float2 q = __half22float2(*(__half2*)&zraw.x); zf[0]=q.x; zf[1]=q.y; }
    { float2 q = __half22float2(*(__half2*)&zraw.y); zf[2]=q.x; zf[3]=q.y; }
    { float2 q = __half22float2(*(__half2*)&zraw.z); zf[4]=q.x; zf[5]=q.y; }
    { float2 q = __half22float2(*(__half2*)&zraw.w); zf[6]=q.x; zf[7]=q.y; }

    __half2 o[4];
    #pragma unroll
    for (int i = 0; i < 4; i++)
        o[i] = __floats2half2_rn(silu(a[2*i]) * silu(zf[2*i]),
                                 silu(a[2*i+1]) * silu(zf[2*i+1]));
    *reinterpret_cast<float4*>(y + (size_t)m * D_INNER + c) = *(float4*)o;
    PDL_FIRE();
}

extern "C" void kernel_launch(void* const* d_in, const int* in_sizes, int n_in,
                              void* d_out, int out_size)
{
    const float* x     = (const float*)d_in[0];
    const float* gamma = (const float*)d_in[1];
    const float* beta  = (const float*)d_in[2];
    const float* W_in  = (const float*)d_in[3];
    const float* cw    = (const float*)d_in[4];
    const float* cb    = (const float*)d_in[5];
    const float* W_out = (const float*)d_in[6];
    float* out = (float*)d_out;

    void *p_xn, *p_win, *p_wout, *p_xz, *p_y, *p_cwt;
    cudaGetSymbolAddress(&p_xn,   g_xn);
    cudaGetSymbolAddress(&p_win,  g_win);
    cudaGetSymbolAddress(&p_wout, g_wout);
    cudaGetSymbolAddress(&p_xz,   g_xz);
    cudaGetSymbolAddress(&p_y,    g_y);
    cudaGetSymbolAddress(&p_cwt,  g_cwt);

    cudaFuncSetAttribute(gemm_f16<true>,
        cudaFuncAttributeMaxDynamicSharedMemorySize, SMEM_DYN);
    cudaFuncSetAttribute(gemm_f16<false>,
        cudaFuncAttributeMaxDynamicSharedMemorySize, SMEM_DYN);

    prep<<<PREP_GRID, 256>>>(x, gamma, beta, (__half*)p_xn,
        W_in, (__half*)p_win, W_out, (__half*)p_wout, cw, (float*)p_cwt);

    cudaLaunchAttribute pdl[1];
    pdl[0].id = cudaLaunchAttributeProgrammaticStreamSerialization;
    pdl[0].val.programmaticStreamSerializationAllowed = 1;

    {   // GEMM1
        cudaLaunchConfig_t cfg = {};
        cfg.gridDim = dim3(N1 / 128, M_TOK / 128);
        cfg.blockDim = dim3(128);
        cfg.dynamicSmemBytes = SMEM_DYN;
        cfg.stream = 0;
        cfg.attrs = pdl; cfg.numAttrs = 1;
        cudaLaunchKernelEx(&cfg, gemm_f16<true>,
            (const __half*)p_xn, (const __half*)p_win,
            (void*)p_xz, (const float*)nullptr, (int)K1, (int)N1);
    }
    {   // conv_gate
        cudaLaunchConfig_t cfg = {};
        cfg.gridDim = dim3(M_TOK);
        cfg.blockDim = dim3(256);
        cfg.stream = 0;
        cfg.attrs = pdl; cfg.numAttrs = 1;
        cudaLaunchKernelEx(&cfg, conv_gate,
            (const __half*)p_xz, (const float*)p_cwt, cb, (__half*)p_y);
    }
    {   // GEMM2
        cudaLaunchConfig_t cfg = {};
        cfg.gridDim = dim3(N2 / 128, M_TOK / 128);
        cfg.blockDim = dim3(128);
        cfg.dynamicSmemBytes = SMEM_DYN;
        cfg.stream = 0;
        cfg.attrs = pdl; cfg.numAttrs = 1;
        cudaLaunchKernelEx(&cfg, gemm_f16<false>,
            (const __half*)p_y, (const __half*)p_wout,
            (void*)out, (const float*)x, (int)K2, (int)N2);
    }
}